// round 1
// baseline (speedup 1.0000x reference)
#include <cuda_runtime.h>
#include <math.h>
#include <stdint.h>

#define NB   256
#define DIN  5000
#define NH1  2048
#define NH2  1024
#define NISO 100000
#define NG   25000

// Scratch (static __device__ arrays: allocation-free per harness rules)
__device__ float g_h1[NB * NH1];
__device__ float g_h2[NB * NH2];
__device__ float g_denom[NB * NG];

__device__ __forceinline__ uint32_t f2tf(float x) {
    uint32_t r;
    asm("cvt.rna.tf32.f32 %0, %1;" : "=r"(r) : "f"(x));
    return r;
}

__device__ __forceinline__ void cp16(float* s, const float* g, bool pred) {
    uint32_t sa = (uint32_t)__cvta_generic_to_shared(s);
    int sz = pred ? 16 : 0;
    asm volatile("cp.async.cg.shared.global [%0], [%1], 16, %2;\n"
                 :: "r"(sa), "l"(g), "r"(sz) : "memory");
}

__device__ __forceinline__ void mma_tf32(float* c, const uint32_t* a, const uint32_t* b) {
    asm volatile(
        "mma.sync.aligned.m16n8k8.row.col.f32.tf32.tf32.f32 "
        "{%0,%1,%2,%3}, {%4,%5,%6,%7}, {%8,%9}, {%0,%1,%2,%3};\n"
        : "+f"(c[0]), "+f"(c[1]), "+f"(c[2]), "+f"(c[3])
        : "r"(a[0]), "r"(a[1]), "r"(a[2]), "r"(a[3]), "r"(b[0]), "r"(b[1]));
}

// MODE 0: out = acc + bias  (plain store)
// MODE 1: e = exp(acc + bias); out = e; atomicAdd(denom[row][idx[col]], e)
template<int BM, int BN, int BK, int WM, int WN, bool PRECISE, int MODE>
__global__ void __launch_bounds__(256)
gemm_tf32_kernel(const float* __restrict__ A, const float* __restrict__ W,
                 const float* __restrict__ bias, float* __restrict__ out,
                 int M, int N, int K,
                 const int* __restrict__ idx, float* __restrict__ denom)
{
    constexpr int S   = 3;
    constexpr int BKP = BK + 4;
    constexpr int BNP = BN + 4;
    constexpr int WARPS_N = BN / WN;
    constexpr int MT  = WM / 16;
    constexpr int NT  = WN / 8;
    constexpr int ACH = BM * BK / 4;   // 16B chunks per A stage
    constexpr int BCH = BK * BN / 4;

    extern __shared__ float smem[];
    float* sAb = smem;
    float* sBb = smem + S * BM * BKP;

    const int tid  = threadIdx.x;
    const int warp = tid >> 5;
    const int lane = tid & 31;
    const int gid  = lane >> 2;   // 0..7
    const int tig  = lane & 3;    // 0..3
    const int wm   = (warp / WARPS_N) * WM;
    const int wn   = (warp % WARPS_N) * WN;
    const int bm   = blockIdx.y * BM;
    const int bn   = blockIdx.x * BN;

    const int T = (K + BK - 1) / BK;

    float acc[MT][NT][4];
#pragma unroll
    for (int i = 0; i < MT; ++i)
#pragma unroll
        for (int j = 0; j < NT; ++j)
#pragma unroll
            for (int r = 0; r < 4; ++r) acc[i][j][r] = 0.f;

    auto load_tile = [&](int t, int stage) {
        const int k0 = t * BK;
        float* sa = sAb + stage * BM * BKP;
        float* sb = sBb + stage * BK * BNP;
#pragma unroll
        for (int i = 0; i < (ACH + 255) / 256; ++i) {
            int c = tid + i * 256;
            if (ACH % 256 == 0 || c < ACH) {
                int row = c / (BK / 4);
                int cc  = c % (BK / 4);
                int kk  = k0 + cc * 4;
                int kc  = kk < K ? kk : 0;  // clamp (unused when pred false)
                cp16(sa + row * BKP + cc * 4,
                     A + (size_t)(bm + row) * K + kc, kk < K);
            }
        }
#pragma unroll
        for (int i = 0; i < (BCH + 255) / 256; ++i) {
            int c = tid + i * 256;
            if (BCH % 256 == 0 || c < BCH) {
                int row = c / (BN / 4);
                int cc  = c % (BN / 4);
                int col = bn + cc * 4;
                int kk  = k0 + row;
                bool p  = (kk < K) && (col < N);
                int kc  = kk < K ? kk : 0;
                int cl  = col < N ? col : 0;
                cp16(sb + row * BNP + cc * 4,
                     W + (size_t)kc * N + cl, p);
            }
        }
        asm volatile("cp.async.commit_group;\n" ::: "memory");
    };

    // prologue: stages 0,1
    load_tile(0, 0);
    if (T > 1) load_tile(1, 1); else asm volatile("cp.async.commit_group;\n" ::: "memory");

    for (int t = 0; t < T; ++t) {
        asm volatile("cp.async.wait_group 1;\n" ::: "memory");
        __syncthreads();
        // issue stage t+2 (safe: every warp is past compute(t-1) here)
        if (t + 2 < T) load_tile(t + 2, (t + 2) % S);
        else asm volatile("cp.async.commit_group;\n" ::: "memory");

        const float* a = sAb + (t % S) * BM * BKP;
        const float* b = sBb + (t % S) * BK * BNP;

#pragma unroll
        for (int ks = 0; ks < BK / 8; ++ks) {
            uint32_t af[MT][4], afl[MT][4];
#pragma unroll
            for (int mt = 0; mt < MT; ++mt) {
                const float* ap = a + (size_t)(wm + mt * 16 + gid) * BKP + ks * 8 + tig;
                float f0 = ap[0];
                float f1 = ap[8 * BKP];
                float f2 = ap[4];
                float f3 = ap[8 * BKP + 4];
                af[mt][0] = f2tf(f0); af[mt][1] = f2tf(f1);
                af[mt][2] = f2tf(f2); af[mt][3] = f2tf(f3);
                if (PRECISE) {
                    afl[mt][0] = f2tf(f0 - __uint_as_float(af[mt][0]));
                    afl[mt][1] = f2tf(f1 - __uint_as_float(af[mt][1]));
                    afl[mt][2] = f2tf(f2 - __uint_as_float(af[mt][2]));
                    afl[mt][3] = f2tf(f3 - __uint_as_float(af[mt][3]));
                }
            }
            uint32_t bf[NT][2], bfl[NT][2];
#pragma unroll
            for (int nt = 0; nt < NT; ++nt) {
                const float* bp = b + (size_t)(ks * 8 + tig) * BNP + wn + nt * 8 + gid;
                float f0 = bp[0];
                float f1 = bp[4 * BNP];
                bf[nt][0] = f2tf(f0); bf[nt][1] = f2tf(f1);
                if (PRECISE) {
                    bfl[nt][0] = f2tf(f0 - __uint_as_float(bf[nt][0]));
                    bfl[nt][1] = f2tf(f1 - __uint_as_float(bf[nt][1]));
                }
            }
#pragma unroll
            for (int mt = 0; mt < MT; ++mt)
#pragma unroll
                for (int nt = 0; nt < NT; ++nt) {
                    if (PRECISE) {
                        mma_tf32(acc[mt][nt], afl[mt], bf[nt]);
                        mma_tf32(acc[mt][nt], af[mt], bfl[nt]);
                    }
                    mma_tf32(acc[mt][nt], af[mt], bf[nt]);
                }
        }
    }

    // epilogue
#pragma unroll
    for (int nt = 0; nt < NT; ++nt) {
        int col0 = bn + wn + nt * 8 + tig * 2;
        int gi0 = 0, gi1 = 0;
        if (MODE == 1) {
            gi0 = (col0 < N)     ? idx[col0]     : 0;
            gi1 = (col0 + 1 < N) ? idx[col0 + 1] : 0;
        }
        float bia0 = (col0 < N)     ? bias[col0]     : 0.f;
        float bia1 = (col0 + 1 < N) ? bias[col0 + 1] : 0.f;
#pragma unroll
        for (int mt = 0; mt < MT; ++mt) {
            int row0 = bm + wm + mt * 16 + gid;
#pragma unroll
            for (int r = 0; r < 4; ++r) {
                int row = row0 + ((r >= 2) ? 8 : 0);
                int col = col0 + (r & 1);
                if (col < N) {
                    float v = acc[mt][nt][r] + ((r & 1) ? bia1 : bia0);
                    if (MODE == 0) {
                        out[(size_t)row * N + col] = v;
                    } else {
                        float e = expf(v);
                        out[(size_t)row * N + col] = e;
                        atomicAdd(&denom[(size_t)row * NG + ((r & 1) ? gi1 : gi0)], e);
                    }
                }
            }
        }
    }
}

// Row-wise LayerNorm (biased var, eps=1e-5) + exact-erf GELU, in place.
__global__ void ln_gelu_kernel(float* __restrict__ h, const float* __restrict__ g,
                               const float* __restrict__ beta, int H)
{
    int row = blockIdx.x;
    float* x = h + (size_t)row * H;
    float s = 0.f, ss = 0.f;
    for (int i = threadIdx.x; i < H; i += blockDim.x) {
        float v = x[i];
        s += v; ss += v * v;
    }
    __shared__ float sh[2][8];
#pragma unroll
    for (int o = 16; o > 0; o >>= 1) {
        s  += __shfl_xor_sync(0xffffffffu, s, o);
        ss += __shfl_xor_sync(0xffffffffu, ss, o);
    }
    int w = threadIdx.x >> 5;
    if ((threadIdx.x & 31) == 0) { sh[0][w] = s; sh[1][w] = ss; }
    __syncthreads();
    float ts = 0.f, tss = 0.f;
#pragma unroll
    for (int i = 0; i < 8; ++i) { ts += sh[0][i]; tss += sh[1][i]; }
    float mu   = ts / (float)H;
    float var  = tss / (float)H - mu * mu;
    float rstd = rsqrtf(var + 1e-5f);
    for (int i = threadIdx.x; i < H; i += blockDim.x) {
        float v = (x[i] - mu) * rstd * g[i] + beta[i];
        x[i] = 0.5f * v * (1.0f + erff(v * 0.70710678118654752f));
    }
}

// out[b,i] = exp_logit / max(denom[b, idx[i]], 1e-8)
__global__ void div_kernel(float* __restrict__ out, const float* __restrict__ denom,
                           const int* __restrict__ idx)
{
    size_t i = (size_t)blockIdx.x * blockDim.x + threadIdx.x;
    size_t total = (size_t)NB * NISO / 4;
    if (i >= total) return;
    size_t e0 = i * 4;
    int b = (int)(e0 / NISO);
    int n = (int)(e0 % NISO);
    float4 v = ((const float4*)out)[i];
    int4 g4 = ((const int4*)idx)[n >> 2];
    const float* drow = denom + (size_t)b * NG;
    v.x /= fmaxf(drow[g4.x], 1e-8f);
    v.y /= fmaxf(drow[g4.y], 1e-8f);
    v.z /= fmaxf(drow[g4.z], 1e-8f);
    v.w /= fmaxf(drow[g4.w], 1e-8f);
    ((float4*)out)[i] = v;
}

extern "C" void kernel_launch(void* const* d_in, const int* in_sizes, int n_in,
                              void* d_out, int out_size)
{
    const float* x   = (const float*)d_in[0];
    const int*   idx = (const int*)  d_in[1];
    const float* W1  = (const float*)d_in[2];
    const float* b1  = (const float*)d_in[3];
    const float* g1  = (const float*)d_in[4];
    const float* be1 = (const float*)d_in[5];
    const float* W2  = (const float*)d_in[6];
    const float* b2  = (const float*)d_in[7];
    const float* g2  = (const float*)d_in[8];
    const float* be2 = (const float*)d_in[9];
    const float* W3  = (const float*)d_in[10];
    const float* b3  = (const float*)d_in[11];
    float* out = (float*)d_out;

    float *h1, *h2, *denom;
    cudaGetSymbolAddress((void**)&h1, g_h1);
    cudaGetSymbolAddress((void**)&h2, g_h2);
    cudaGetSymbolAddress((void**)&denom, g_denom);

    cudaMemsetAsync(denom, 0, sizeof(float) * NB * NG);

    // ---- Layer 1: x[256,5000] @ W1[5000,2048] + b1 (tf32x3 for accuracy) ----
    {
        constexpr int BM = 64, BN = 64, BK = 16, WM = 32, WN = 16;
        constexpr int SM = 3 * (BM * (BK + 4) + BK * (BN + 4)) * 4;
        auto k = gemm_tf32_kernel<BM, BN, BK, WM, WN, true, 0>;
        cudaFuncSetAttribute(k, cudaFuncAttributeMaxDynamicSharedMemorySize, SM);
        dim3 grid(NH1 / BN, NB / BM);
        k<<<grid, 256, SM>>>(x, W1, b1, h1, NB, NH1, DIN, nullptr, nullptr);
    }
    ln_gelu_kernel<<<NB, 256>>>(h1, g1, be1, NH1);

    // ---- Layer 2: h1[256,2048] @ W2[2048,1024] + b2 (tf32x3) ----
    {
        constexpr int BM = 64, BN = 64, BK = 16, WM = 32, WN = 16;
        constexpr int SM = 3 * (BM * (BK + 4) + BK * (BN + 4)) * 4;
        auto k = gemm_tf32_kernel<BM, BN, BK, WM, WN, true, 0>;
        cudaFuncSetAttribute(k, cudaFuncAttributeMaxDynamicSharedMemorySize, SM);
        dim3 grid(NH2 / BN, NB / BM);
        k<<<grid, 256, SM>>>(h1, W2, b2, h2, NB, NH2, NH1, nullptr, nullptr);
    }
    ln_gelu_kernel<<<NB, 256>>>(h2, g2, be2, NH2);

    // ---- Layer 3: h2[256,1024] @ W3[1024,100000] + b3 -> exp + per-gene denom ----
    {
        constexpr int BM = 128, BN = 128, BK = 16, WM = 64, WN = 32;
        constexpr int SM = 3 * (BM * (BK + 4) + BK * (BN + 4)) * 4;
        auto k = gemm_tf32_kernel<BM, BN, BK, WM, WN, false, 1>;
        cudaFuncSetAttribute(k, cudaFuncAttributeMaxDynamicSharedMemorySize, SM);
        dim3 grid((NISO + BN - 1) / BN, NB / BM);
        k<<<grid, 256, SM>>>(h2, W3, b3, out, NB, NISO, NH2, idx, denom);
    }

    // ---- Grouped-softmax normalize ----
    {
        int total4 = NB * NISO / 4;
        div_kernel<<<(total4 + 255) / 256, 256>>>(out, denom, idx);
    }
}